// round 5
// baseline (speedup 1.0000x reference)
#include <cuda_runtime.h>
#include <math.h>

#define RBM_B 2048
#define RBM_V 4096
#define RBM_H 1024

// Scratch (device globals: allocation-free rule)
static __device__ float g_WT[(size_t)RBM_H * RBM_V];   // 16 MB  W transposed [H,V]
static __device__ float g_h [(size_t)RBM_B * RBM_H];   //  8 MB  current h (binary as float)
static __device__ float g_v [(size_t)RBM_B * RBM_V];   // 32 MB  current v (binary as float)
static __device__ float g_pos[RBM_B * 16];             // pos score partials (8 n-tiles used)
static __device__ float g_neg[RBM_B * 64];             // neg score partials (32 n-tiles used)

typedef unsigned long long u64;

// packed f32x2 FMA (full-rate fp32 on sm_103a; per-lane rounding identical to scalar FFMA)
__device__ __forceinline__ void ffma2(u64& d, u64 a, u64 b) {
    asm("fma.rn.f32x2 %0, %1, %2, %0;" : "+l"(d) : "l"(a), "l"(b));
}
__device__ __forceinline__ u64 dup32(float v) {
    unsigned u = __float_as_uint(v);
    return (u64)u | ((u64)u << 32);
}

// ---------------- transpose W[V,H] -> WT[H,V] ----------------
__global__ void k_transpose(const float* __restrict__ W, float* __restrict__ WT) {
    __shared__ float t[32][33];
    int h0 = blockIdx.x * 32, v0 = blockIdx.y * 32;
#pragma unroll
    for (int i = 0; i < 4; ++i)
        t[threadIdx.y + 8*i][threadIdx.x] =
            W[(size_t)(v0 + threadIdx.y + 8*i) * RBM_H + h0 + threadIdx.x];
    __syncthreads();
#pragma unroll
    for (int i = 0; i < 4; ++i)
        WT[(size_t)(h0 + threadIdx.y + 8*i) * RBM_V + v0 + threadIdx.x] =
            t[threadIdx.x][threadIdx.y + 8*i];
}

// ---------------- fused GEMM + bias + sigmoid-Bernoulli sample (+score) ----------------
// C[M,N] = A[M,K] * Bm[K,N]; A binary {0,1} (products exact).
// CRITICAL: single accumulator per output element, strict ascending-k fma.rn.f32x2 chain
// (bit-identical logits to the round-3/4 passing kernels).
// MP = m-pairs per thread: MP=4 -> BM=64 (V-out, big grids); MP=2 -> BM=32 (H-out,
// doubles CTA count to fix grid-limited occupancy). BN=128, BK=16, 128 threads.
template<int SCORE, int MP>
__global__ __launch_bounds__(128, (MP == 2 ? 5 : 4))
void k_gemm_sample(const float* __restrict__ A, const float* __restrict__ Bm,
                   const float* __restrict__ bias, const float* __restrict__ U,
                   float* __restrict__ Out, float* __restrict__ Score,
                   int K, int N)
{
    constexpr int BM = MP * 16, BN = 128, BK = 16;
    __shared__ __align__(16) float As[2][BK][BM];
    // Bs: duplicated pairs as u64, [kk][j(0..7)][tx(0..15)] -> inner read Bu[j*16+tx]
    // is a conflict-free 2-way-broadcast 128B wavefront (LDS.64).
    __shared__ __align__(16) u64 Bs[2][BK][BN];

    const int tid = threadIdx.x;
    const int tx = tid & 15, ty = tid >> 4;              // 16 x 8 threads; tile (MP*2)m x 8n
    const int m0 = blockIdx.y * BM, n0 = blockIdx.x * BN;

    // A load: BM*BK floats, BM/8 per thread (float4-granular)
    const int arow = (MP == 4) ? (tid >> 1) : (tid >> 2);
    const int acol = (MP == 4) ? ((tid & 1) * 8) : ((tid & 3) * 4);
    const int brow = tid >> 3;                           // B: 16 rows, 16 consecutive n each
    const int bcol = (tid & 7) * 16;

    const float* Aload = A + (size_t)(m0 + arow) * K + acol;
    const float* Bload = Bm + (size_t)brow * N + n0 + bcol;

    u64 acc[MP][8];
#pragma unroll
    for (int p = 0; p < MP; ++p)
#pragma unroll
        for (int j = 0; j < 8; ++j) acc[p][j] = 0ull;

    float4 pa[2], pb[4];
    constexpr int AF = (MP == 4) ? 2 : 1;                // float4s of A per thread

    // ---- prologue: tile 0 ----
#pragma unroll
    for (int q = 0; q < AF; ++q) pa[q] = *(const float4*)(Aload + q * 4);
#pragma unroll
    for (int q = 0; q < 4; ++q) pb[q] = *(const float4*)(Bload + q * 4);
    {
#pragma unroll
        for (int c = 0; c < AF * 4; ++c)
            As[0][acol + c][arow] = ((const float*)&pa[0])[c];
        u64* bd = &Bs[0][brow][0];
#pragma unroll
        for (int i = 0; i < 16; ++i) {
            float v = ((const float*)&pb[0])[i];
            int nl = bcol + i;
            bd[(nl & 7) * 16 + (nl >> 3)] = dup32(v);
        }
    }
    __syncthreads();

    const int nk = K / BK;
    int buf = 0;
    for (int t = 0; t < nk; ++t) {
        if (t + 1 < nk) {
            const float* Ap = Aload + (t + 1) * BK;
#pragma unroll
            for (int q = 0; q < AF; ++q) pa[q] = *(const float4*)(Ap + q * 4);
            const float* Bp = Bload + (size_t)(t + 1) * BK * N;
#pragma unroll
            for (int q = 0; q < 4; ++q) pb[q] = *(const float4*)(Bp + q * 4);
        }
        // strict ascending-k serial accumulation (MP*8 independent FFMA2 chains)
#pragma unroll
        for (int kk = 0; kk < BK; ++kk) {
            const ulonglong2* Au = (const ulonglong2*)&As[buf][kk][0];
            u64 ap[MP];
            if (MP == 4) {
                ulonglong2 A01 = Au[ty * 2], A23 = Au[ty * 2 + 1];
                ap[0] = A01.x; ap[1] = A01.y; ap[2] = A23.x; ap[3] = A23.y;
            } else {
                ulonglong2 A01 = Au[ty];
                ap[0] = A01.x; ap[1] = A01.y;
            }
            const u64* Bu = &Bs[buf][kk][0];
            u64 bp[8];
#pragma unroll
            for (int j = 0; j < 8; ++j) bp[j] = Bu[j * 16 + tx];
#pragma unroll
            for (int p = 0; p < MP; ++p)
#pragma unroll
                for (int j = 0; j < 8; ++j)
                    ffma2(acc[p][j], ap[p], bp[j]);
        }
        if (t + 1 < nk) {
            int nb = buf ^ 1;
#pragma unroll
            for (int c = 0; c < AF * 4; ++c)
                As[nb][acol + c][arow] = ((const float*)&pa[0])[c];
            u64* bd = &Bs[nb][brow][0];
#pragma unroll
            for (int i = 0; i < 16; ++i) {
                float v = ((const float*)&pb[0])[i];
                int nl = bcol + i;
                bd[(nl & 7) * 16 + (nl >> 3)] = dup32(v);
            }
        }
        __syncthreads();
        buf ^= 1;
    }

    // ---- epilogue: bias + sigmoid + Bernoulli + optional per-row score partial ----
    const int gnb = n0 + tx * 8;
    float bias8[8];
    *(float4*)&bias8[0] = *(const float4*)(bias + gnb);
    *(float4*)&bias8[4] = *(const float4*)(bias + gnb + 4);
#pragma unroll
    for (int p = 0; p < MP; ++p) {
#pragma unroll
        for (int half = 0; half < 2; ++half) {
            int gm = m0 + ty * (MP * 2) + p * 2 + half;
            float u8[8];
            *(float4*)&u8[0] = *(const float4*)(U + (size_t)gm * N + gnb);
            *(float4*)&u8[4] = *(const float4*)(U + (size_t)gm * N + gnb + 4);
            float l[8], s[8];
#pragma unroll
            for (int j = 0; j < 8; ++j) {
                float2 a2 = *(float2*)&acc[p][j];
                float c = half ? a2.y : a2.x;
                l[j] = c + bias8[j];
                float pr = 1.0f / (1.0f + expf(-l[j]));   // libdevice expf + IEEE div
                s[j] = (pr > u8[j]) ? 1.0f : 0.0f;
            }
            *(float4*)(Out + (size_t)gm * N + gnb)     = make_float4(s[0], s[1], s[2], s[3]);
            *(float4*)(Out + (size_t)gm * N + gnb + 4) = make_float4(s[4], s[5], s[6], s[7]);
            if (SCORE) {
                float sp = 0.f;
#pragma unroll
                for (int j = 0; j < 8; ++j) sp += s[j] * l[j];
#pragma unroll
                for (int off = 8; off; off >>= 1)
                    sp += __shfl_xor_sync(0xffffffffu, sp, off);
                if (tx == 0) Score[(size_t)gm * gridDim.x + blockIdx.x] = sp;
            }
        }
    }
}

// ---------------- finalize: out[b] = (v.b_v + pos) - (neg + h2.b_h) ----------------
__global__ void k_finalize(const float* __restrict__ visible, const float* __restrict__ b_v,
                           const float* __restrict__ b_h, float* __restrict__ out)
{
    int b = blockIdx.x, tid = threadIdx.x;
    float acc = 0.f;
    const float* vr = visible + (size_t)b * RBM_V;
    for (int i = tid; i < RBM_V; i += 256) acc += vr[i] * b_v[i];
    const float* hr = g_h + (size_t)b * RBM_H;            // g_h holds h2 here
    for (int i = tid; i < RBM_H; i += 256) acc -= hr[i] * b_h[i];
    if (tid < 8)  acc += g_pos[b * 8 + tid];              // 8 n-tiles (BN=128, N=1024)
    if (tid < 32) acc -= g_neg[b * 32 + tid];             // 32 n-tiles (BN=128, N=4096)
    __shared__ float red[256];
    red[tid] = acc;
    __syncthreads();
    for (int o = 128; o; o >>= 1) { if (tid < o) red[tid] += red[tid + o]; __syncthreads(); }
    if (tid == 0) out[b] = red[0];
}

// ---------------- launch ----------------
extern "C" void kernel_launch(void* const* d_in, const int* in_sizes, int n_in,
                              void* d_out, int out_size)
{
    const float* visible = (const float*)d_in[0];
    const float* b_v     = (const float*)d_in[1];
    const float* b_h     = (const float*)d_in[2];
    const float* W       = (const float*)d_in[3];
    const float* u_h0    = (const float*)d_in[4];
    const float* u_v     = (const float*)d_in[5];
    const float* u_h     = (const float*)d_in[6];
    float* out = (float*)d_out;

    float *WT, *hb, *vb, *pos, *neg;
    cudaGetSymbolAddress((void**)&WT,  g_WT);
    cudaGetSymbolAddress((void**)&hb,  g_h);
    cudaGetSymbolAddress((void**)&vb,  g_v);
    cudaGetSymbolAddress((void**)&pos, g_pos);
    cudaGetSymbolAddress((void**)&neg, g_neg);

    k_transpose<<<dim3(RBM_H / 32, RBM_V / 32), dim3(32, 8)>>>(W, WT);

    dim3 blk(128);
    dim3 gH(RBM_H / 128, RBM_B / 32);   // (8, 64)  = 512 CTAs, BM=32 (MP=2)
    dim3 gV(RBM_V / 128, RBM_B / 64);   // (32, 32) = 1024 CTAs, BM=64 (MP=4)

    const size_t BV = (size_t)RBM_B * RBM_V;
    const size_t BH = (size_t)RBM_B * RBM_H;

    // positive phase: h0 | data, fused pos-score
    k_gemm_sample<1,2><<<gH, blk>>>(visible, W,  b_h, u_h0,        hb, pos,    RBM_V, RBM_H);
    // Gibbs chain: v,h,v,h,v
    k_gemm_sample<0,4><<<gV, blk>>>(hb,      WT, b_v, u_v + 0*BV,  vb, nullptr, RBM_H, RBM_V);
    k_gemm_sample<0,2><<<gH, blk>>>(vb,      W,  b_h, u_h + 0*BH,  hb, nullptr, RBM_V, RBM_H);
    k_gemm_sample<0,4><<<gV, blk>>>(hb,      WT, b_v, u_v + 1*BV,  vb, nullptr, RBM_H, RBM_V);
    k_gemm_sample<0,2><<<gH, blk>>>(vb,      W,  b_h, u_h + 1*BH,  hb, nullptr, RBM_V, RBM_H);
    // last v-step: fused neg-score
    k_gemm_sample<2,4><<<gV, blk>>>(hb,      WT, b_v, u_v + 2*BV,  vb, neg,     RBM_H, RBM_V);

    k_finalize<<<RBM_B, 256>>>(visible, b_v, b_h, out);
}

// round 6
// speedup vs baseline: 1.1958x; 1.1958x over previous
#include <cuda_runtime.h>
#include <math.h>

#define RBM_B 2048
#define RBM_V 4096
#define RBM_H 1024

// Scratch (device globals: allocation-free rule)
static __device__ float g_WT[(size_t)RBM_H * RBM_V];   // 16 MB  W transposed [H,V]
static __device__ float g_h [(size_t)RBM_B * RBM_H];   //  8 MB  current h
static __device__ float g_v [(size_t)RBM_B * RBM_V];   // 32 MB  current v
static __device__ float g_pos[RBM_B * 16];             // pos partials (16 n-tiles, BN=64)
static __device__ float g_neg[RBM_B * 32];             // neg partials (32 n-tiles, BN=128)

typedef unsigned long long u64;

// packed f32x2 FMA (full-rate fp32 on sm_103a; per-lane rounding == scalar FFMA)
__device__ __forceinline__ void ffma2(u64& d, u64 a, u64 b) {
    asm("fma.rn.f32x2 %0, %1, %2, %0;" : "+l"(d) : "l"(a), "l"(b));
}
__device__ __forceinline__ u64 dup32(float v) {
    unsigned u = __float_as_uint(v);
    return (u64)u | ((u64)u << 32);
}

// ---------------- transpose W[V,H] -> WT[H,V] ----------------
__global__ void k_transpose(const float* __restrict__ W, float* __restrict__ WT) {
    __shared__ float t[32][33];
    int h0 = blockIdx.x * 32, v0 = blockIdx.y * 32;
#pragma unroll
    for (int i = 0; i < 4; ++i)
        t[threadIdx.y + 8*i][threadIdx.x] =
            W[(size_t)(v0 + threadIdx.y + 8*i) * RBM_H + h0 + threadIdx.x];
    __syncthreads();
#pragma unroll
    for (int i = 0; i < 4; ++i)
        WT[(size_t)(h0 + threadIdx.y + 8*i) * RBM_V + v0 + threadIdx.x] =
            t[threadIdx.x][threadIdx.y + 8*i];
}

// ---------------- fused GEMM + bias + sigmoid-Bernoulli sample (+score) ----------------
// C[M,N] = A[M,K] * Bm[K,N]; A binary {0,1}.
// CRITICAL: one accumulator per element, strict ascending-k fma.rn chain (bit-identical
// logits to all prior passing kernels). SIMD pairing along n: acc[m][j] = (n2j, n2j+1).
// A is duplicated in smem (broadcast reads); B is plain float (vector LDS.128 reads).
// BM=64, BK=16, 128 threads (tx=16 n-groups, ty=8 m-groups), thread tile 8m x (2*NP)n.
// NP=4 -> BN=128 (V-out); NP=2 -> BN=64 (H-out, grid 512 fixes occupancy).
template<int SCORE, int NP>
__global__ __launch_bounds__(128, (NP == 2 ? 5 : 4))
void k_gemm_sample(const float* __restrict__ A, const float* __restrict__ Bm,
                   const float* __restrict__ bias, const float* __restrict__ U,
                   float* __restrict__ Out, float* __restrict__ Score,
                   int K, int N)
{
    constexpr int BM = 64, BN = NP * 32, BK = 16;
    __shared__ __align__(16) u64   As[2][BK][BM];       // dup-A: 16 KB
    __shared__ __align__(16) float Bs[2][BK][BN];       // plain B: 8/16 KB

    const int tid = threadIdx.x;
    const int tx = tid & 15, ty = tid >> 4;
    const int m0 = blockIdx.y * BM, n0 = blockIdx.x * BN;

    const int arow = tid >> 1;                          // A: 64 rows, 8 consecutive k each
    const int acol = (tid & 1) * 8;
    constexpr int BTH = BN * BK / 128;                  // floats of B per thread (8 or 16)
    const int brow = tid / (BN / BTH);                  // B rows covered by (128*BTH)/BN
    const int bcol = (tid % (BN / BTH)) * BTH;

    const float* Aload = A + (size_t)(m0 + arow) * K + acol;
    const float* Bload = Bm + (size_t)brow * N + n0 + bcol;

    // acc[m 0..7][j 0..NP-1]; u64 = fp32 pair for columns (2j, 2j+1), row m
    u64 acc[8][NP];
#pragma unroll
    for (int m = 0; m < 8; ++m)
#pragma unroll
        for (int j = 0; j < NP; ++j) acc[m][j] = 0ull;

    float4 pa[2], pb[4];
    constexpr int BF = BTH / 4;                         // float4s of B per thread (2 or 4)

    // ---- prologue: tile 0 ----
    pa[0] = *(const float4*)(Aload);
    pa[1] = *(const float4*)(Aload + 4);
#pragma unroll
    for (int q = 0; q < BF; ++q) pb[q] = *(const float4*)(Bload + q * 4);
    {
#pragma unroll
        for (int c = 0; c < 8; ++c)
            As[0][acol + c][arow] = dup32(((const float*)&pa[0])[c]);
#pragma unroll
        for (int q = 0; q < BF; ++q)
            *(float4*)&Bs[0][brow][bcol + q * 4] = pb[q];
    }
    __syncthreads();

    const int nk = K / BK;
    int buf = 0;
    for (int t = 0; t < nk; ++t) {
        if (t + 1 < nk) {
            const float* Ap = Aload + (t + 1) * BK;
            pa[0] = *(const float4*)(Ap);
            pa[1] = *(const float4*)(Ap + 4);
            const float* Bp = Bload + (size_t)(t + 1) * BK * N;
#pragma unroll
            for (int q = 0; q < BF; ++q) pb[q] = *(const float4*)(Bp + q * 4);
        }
        // strict ascending-k serial accumulation (8*NP independent FFMA2 chains)
#pragma unroll
        for (int kk = 0; kk < BK; ++kk) {
            const ulonglong2* Au = (const ulonglong2*)&As[buf][kk][ty * 8];
            ulonglong2 a01 = Au[0], a23 = Au[1], a45 = Au[2], a67 = Au[3];
            u64 ap[8] = {a01.x, a01.y, a23.x, a23.y, a45.x, a45.y, a67.x, a67.y};
            const ulonglong2* Bu = (const ulonglong2*)&Bs[buf][kk][tx * (NP * 2)];
            u64 bp[NP];
#pragma unroll
            for (int q = 0; q < NP / 2; ++q) {
                ulonglong2 b2 = Bu[q];
                bp[q * 2] = b2.x; bp[q * 2 + 1] = b2.y;
            }
#pragma unroll
            for (int m = 0; m < 8; ++m)
#pragma unroll
                for (int j = 0; j < NP; ++j)
                    ffma2(acc[m][j], ap[m], bp[j]);
        }
        if (t + 1 < nk) {
            int nb = buf ^ 1;
#pragma unroll
            for (int c = 0; c < 8; ++c)
                As[nb][acol + c][arow] = dup32(((const float*)&pa[0])[c]);
#pragma unroll
            for (int q = 0; q < BF; ++q)
                *(float4*)&Bs[nb][brow][bcol + q * 4] = pb[q];
        }
        __syncthreads();
        buf ^= 1;
    }

    // ---- epilogue: bias + sigmoid + Bernoulli + optional per-row score partial ----
    constexpr int TN = NP * 2;                          // n per thread (4 or 8)
    const int gnb = n0 + tx * TN;
    float biasN[TN];
#pragma unroll
    for (int q = 0; q < NP / 2; ++q)
        *(float4*)&biasN[q * 4] = *(const float4*)(bias + gnb + q * 4);
#pragma unroll
    for (int m = 0; m < 8; ++m) {
        int gm = m0 + ty * 8 + m;
        float uN[TN];
#pragma unroll
        for (int q = 0; q < NP / 2; ++q)
            *(float4*)&uN[q * 4] = *(const float4*)(U + (size_t)gm * N + gnb + q * 4);
        float l[TN], s[TN];
#pragma unroll
        for (int j = 0; j < NP; ++j) {
            float2 a2 = *(float2*)&acc[m][j];
            l[j*2]   = a2.x + biasN[j*2];
            l[j*2+1] = a2.y + biasN[j*2+1];
        }
#pragma unroll
        for (int j = 0; j < TN; ++j) {
            float pr = 1.0f / (1.0f + expf(-l[j]));     // libdevice expf + IEEE div
            s[j] = (pr > uN[j]) ? 1.0f : 0.0f;
        }
#pragma unroll
        for (int q = 0; q < NP / 2; ++q)
            *(float4*)(Out + (size_t)gm * N + gnb + q * 4) =
                make_float4(s[q*4], s[q*4+1], s[q*4+2], s[q*4+3]);
        if (SCORE) {
            float sp = 0.f;
#pragma unroll
            for (int j = 0; j < TN; ++j) sp += s[j] * l[j];
#pragma unroll
            for (int off = 8; off; off >>= 1)
                sp += __shfl_xor_sync(0xffffffffu, sp, off);
            if (tx == 0) Score[(size_t)gm * gridDim.x + blockIdx.x] = sp;
        }
    }
}

// ---------------- finalize: out[b] = (v.b_v + pos) - (neg + h2.b_h) ----------------
__global__ void k_finalize(const float* __restrict__ visible, const float* __restrict__ b_v,
                           const float* __restrict__ b_h, float* __restrict__ out)
{
    int b = blockIdx.x, tid = threadIdx.x;
    float acc = 0.f;
    const float* vr = visible + (size_t)b * RBM_V;
    for (int i = tid; i < RBM_V; i += 256) acc += vr[i] * b_v[i];
    const float* hr = g_h + (size_t)b * RBM_H;            // g_h holds h2 here
    for (int i = tid; i < RBM_H; i += 256) acc -= hr[i] * b_h[i];
    if (tid < 16) acc += g_pos[b * 16 + tid];             // 16 n-tiles (BN=64, N=1024)
    if (tid < 32) acc -= g_neg[b * 32 + tid];             // 32 n-tiles (BN=128, N=4096)
    __shared__ float red[256];
    red[tid] = acc;
    __syncthreads();
    for (int o = 128; o; o >>= 1) { if (tid < o) red[tid] += red[tid + o]; __syncthreads(); }
    if (tid == 0) out[b] = red[0];
}

// ---------------- launch ----------------
extern "C" void kernel_launch(void* const* d_in, const int* in_sizes, int n_in,
                              void* d_out, int out_size)
{
    const float* visible = (const float*)d_in[0];
    const float* b_v     = (const float*)d_in[1];
    const float* b_h     = (const float*)d_in[2];
    const float* W       = (const float*)d_in[3];
    const float* u_h0    = (const float*)d_in[4];
    const float* u_v     = (const float*)d_in[5];
    const float* u_h     = (const float*)d_in[6];
    float* out = (float*)d_out;

    float *WT, *hb, *vb, *pos, *neg;
    cudaGetSymbolAddress((void**)&WT,  g_WT);
    cudaGetSymbolAddress((void**)&hb,  g_h);
    cudaGetSymbolAddress((void**)&vb,  g_v);
    cudaGetSymbolAddress((void**)&pos, g_pos);
    cudaGetSymbolAddress((void**)&neg, g_neg);

    k_transpose<<<dim3(RBM_H / 32, RBM_V / 32), dim3(32, 8)>>>(W, WT);

    dim3 blk(128);
    dim3 gH(RBM_H / 64,  RBM_B / 64);   // (16, 32) = 512 CTAs, BN=64  (NP=2)
    dim3 gV(RBM_V / 128, RBM_B / 64);   // (32, 32) = 1024 CTAs, BN=128 (NP=4)

    const size_t BV = (size_t)RBM_B * RBM_V;
    const size_t BH = (size_t)RBM_B * RBM_H;

    // positive phase: h0 | data, fused pos-score
    k_gemm_sample<1,2><<<gH, blk>>>(visible, W,  b_h, u_h0,        hb, pos,    RBM_V, RBM_H);
    // Gibbs chain: v,h,v,h,v
    k_gemm_sample<0,4><<<gV, blk>>>(hb,      WT, b_v, u_v + 0*BV,  vb, nullptr, RBM_H, RBM_V);
    k_gemm_sample<0,2><<<gH, blk>>>(vb,      W,  b_h, u_h + 0*BH,  hb, nullptr, RBM_V, RBM_H);
    k_gemm_sample<0,4><<<gV, blk>>>(hb,      WT, b_v, u_v + 1*BV,  vb, nullptr, RBM_H, RBM_V);
    k_gemm_sample<0,2><<<gH, blk>>>(vb,      W,  b_h, u_h + 1*BH,  hb, nullptr, RBM_V, RBM_H);
    // last v-step: fused neg-score
    k_gemm_sample<2,4><<<gV, blk>>>(hb,      WT, b_v, u_v + 2*BV,  vb, neg,     RBM_H, RBM_V);

    k_finalize<<<RBM_B, 256>>>(visible, b_v, b_h, out);
}

// round 7
// speedup vs baseline: 1.4498x; 1.2124x over previous
#include <cuda_runtime.h>
#include <math.h>

#define RBM_B 2048
#define RBM_V 4096
#define RBM_H 1024

// Scratch (device globals: allocation-free rule)
static __device__ float g_WT[(size_t)RBM_H * RBM_V];   // 16 MB  W transposed [H,V]
static __device__ float g_h [(size_t)RBM_B * RBM_H];   //  8 MB  current h
static __device__ float g_v [(size_t)RBM_B * RBM_V];   // 32 MB  current v
static __device__ float g_pos[RBM_B * 8];              // pos partials (8 n-tiles, BN=128)
static __device__ float g_neg[RBM_B * 32];             // neg partials (32 n-tiles, BN=128)

typedef unsigned long long u64;

// packed f32x2 FMA (full-rate fp32 on sm_103a; per-lane rounding == scalar FFMA)
__device__ __forceinline__ void ffma2(u64& d, u64 a, u64 b) {
    asm("fma.rn.f32x2 %0, %1, %2, %0;" : "+l"(d) : "l"(a), "l"(b));
}
__device__ __forceinline__ u64 dup32(float v) {
    unsigned u = __float_as_uint(v);
    return (u64)u | ((u64)u << 32);
}

// ---------------- transpose W[V,H] -> WT[H,V] ----------------
__global__ void k_transpose(const float* __restrict__ W, float* __restrict__ WT) {
    __shared__ float t[32][33];
    int h0 = blockIdx.x * 32, v0 = blockIdx.y * 32;
#pragma unroll
    for (int i = 0; i < 4; ++i)
        t[threadIdx.y + 8*i][threadIdx.x] =
            W[(size_t)(v0 + threadIdx.y + 8*i) * RBM_H + h0 + threadIdx.x];
    __syncthreads();
#pragma unroll
    for (int i = 0; i < 4; ++i)
        WT[(size_t)(h0 + threadIdx.y + 8*i) * RBM_V + v0 + threadIdx.x] =
            t[threadIdx.x][threadIdx.y + 8*i];
}

// ---------------- fused GEMM + bias + sigmoid-Bernoulli sample (+score) ----------------
// C[M,N] = A[M,K] * Bm[K,N]; A binary {0,1}.
// CRITICAL: one accumulator per output element, strict ascending-k fma.rn chain
// (bit-identical logits to all passing rounds). SIMD pairs along n.
// Thread tile 8m x 16n (64 FFMA2 vs 8 conflict-free LDS.128 per kk).
// 128 threads: tx = tid&7 (n), ty = tid>>3 (m). BM = BN = 128, BK = 16.
// Thread n-columns: 4 chunks of 4 at n = q*32 + tx*4 (q = 0..3) -> B reads and all
// epilogue accesses are 128B-contiguous per octet.
template<int SCORE>
__global__ __launch_bounds__(128, 2)
void k_gemm_sample(const float* __restrict__ A, const float* __restrict__ Bm,
                   const float* __restrict__ bias, const float* __restrict__ U,
                   float* __restrict__ Out, float* __restrict__ Score,
                   int K, int N)
{
    constexpr int BM = 128, BN = 128, BK = 16;
    __shared__ __align__(16) u64   As[2][BK][BM];      // dup-A: 32 KB
    __shared__ __align__(16) float Bs[2][BK][BN];      // plain B: 16 KB

    const int tid = threadIdx.x;
    const int tx = tid & 7, ty = tid >> 3;
    const int m0 = blockIdx.y * BM, n0 = blockIdx.x * BN;

    // A: one row per thread, 16 consecutive k. B: one k-row per octet, 16 cols.
    const int brow = tid >> 3, bcol = (tid & 7) * 16;
    const float* Aload = A + (size_t)(m0 + tid) * K;
    const float* Bload = Bm + (size_t)brow * N + n0 + bcol;

    // acc[m 0..7][j 0..7]: u64 = fp32 pair, columns (q*32 + tx*4 + 2r, +1), q=j>>1, r=j&1
    u64 acc[8][8];
#pragma unroll
    for (int m = 0; m < 8; ++m)
#pragma unroll
        for (int j = 0; j < 8; ++j) acc[m][j] = 0ull;

    float4 pa[4], pb[4];

    // ---- prologue: tile 0 ----
#pragma unroll
    for (int q = 0; q < 4; ++q) {
        pa[q] = *(const float4*)(Aload + q * 4);
        pb[q] = *(const float4*)(Bload + q * 4);
    }
    {
#pragma unroll
        for (int c = 0; c < 16; ++c)
            As[0][c][tid] = dup32(((const float*)&pa[0])[c]);
#pragma unroll
        for (int q = 0; q < 4; ++q)
            *(float4*)&Bs[0][brow][bcol + q * 4] = pb[q];
    }
    __syncthreads();

    const int nk = K / BK;
    int buf = 0;
    for (int t = 0; t < nk; ++t) {
        if (t + 1 < nk) {
            const float* Ap = Aload + (t + 1) * BK;
            const float* Bp = Bload + (size_t)(t + 1) * BK * N;
#pragma unroll
            for (int q = 0; q < 4; ++q) {
                pa[q] = *(const float4*)(Ap + q * 4);
                pb[q] = *(const float4*)(Bp + q * 4);
            }
        }
        // strict ascending-k serial accumulation (64 independent FFMA2 chains)
#pragma unroll
        for (int kk = 0; kk < BK; ++kk) {
            const ulonglong2* Au = (const ulonglong2*)&As[buf][kk][ty * 8];
            ulonglong2 a01 = Au[0], a23 = Au[1], a45 = Au[2], a67 = Au[3];
            u64 ap[8] = {a01.x, a01.y, a23.x, a23.y, a45.x, a45.y, a67.x, a67.y};
            u64 bp[8];
#pragma unroll
            for (int q = 0; q < 4; ++q) {
                ulonglong2 b2 = *(const ulonglong2*)&Bs[buf][kk][q * 32 + tx * 4];
                bp[q * 2] = b2.x; bp[q * 2 + 1] = b2.y;
            }
#pragma unroll
            for (int m = 0; m < 8; ++m)
#pragma unroll
                for (int j = 0; j < 8; ++j)
                    ffma2(acc[m][j], ap[m], bp[j]);
        }
        if (t + 1 < nk) {
            int nb = buf ^ 1;
#pragma unroll
            for (int c = 0; c < 16; ++c)
                As[nb][c][tid] = dup32(((const float*)&pa[0])[c]);
#pragma unroll
            for (int q = 0; q < 4; ++q)
                *(float4*)&Bs[nb][brow][bcol + q * 4] = pb[q];
        }
        __syncthreads();
        buf ^= 1;
    }

    // ---- epilogue: bias + sigmoid + Bernoulli + optional per-row score partial ----
    float biasv[16];
#pragma unroll
    for (int q = 0; q < 4; ++q)
        *(float4*)&biasv[q * 4] = *(const float4*)(bias + n0 + q * 32 + tx * 4);
#pragma unroll
    for (int m = 0; m < 8; ++m) {
        int gm = m0 + ty * 8 + m;
        float sp = 0.f;
#pragma unroll
        for (int q = 0; q < 4; ++q) {
            int gn = n0 + q * 32 + tx * 4;
            float4 u4 = *(const float4*)(U + (size_t)gm * N + gn);
            float2 e0 = *(float2*)&acc[m][q * 2];
            float2 e1 = *(float2*)&acc[m][q * 2 + 1];
            float l[4] = { e0.x + biasv[q*4],   e0.y + biasv[q*4+1],
                           e1.x + biasv[q*4+2], e1.y + biasv[q*4+3] };
            float s[4];
#pragma unroll
            for (int j = 0; j < 4; ++j) {
                float pr = 1.0f / (1.0f + expf(-l[j]));   // libdevice expf + IEEE div
                s[j] = (pr > ((const float*)&u4)[j]) ? 1.0f : 0.0f;
            }
            *(float4*)(Out + (size_t)gm * N + gn) = make_float4(s[0], s[1], s[2], s[3]);
            if (SCORE) sp += s[0]*l[0] + s[1]*l[1] + s[2]*l[2] + s[3]*l[3];
        }
        if (SCORE) {
            sp += __shfl_xor_sync(0xffffffffu, sp, 1);
            sp += __shfl_xor_sync(0xffffffffu, sp, 2);
            sp += __shfl_xor_sync(0xffffffffu, sp, 4);
            if (tx == 0) Score[(size_t)gm * gridDim.x + blockIdx.x] = sp;
        }
    }
}

// ---------------- finalize: out[b] = (v.b_v + pos) - (neg + h2.b_h) ----------------
__global__ void k_finalize(const float* __restrict__ visible, const float* __restrict__ b_v,
                           const float* __restrict__ b_h, float* __restrict__ out)
{
    int b = blockIdx.x, tid = threadIdx.x;
    float acc = 0.f;
    const float* vr = visible + (size_t)b * RBM_V;
    for (int i = tid; i < RBM_V; i += 256) acc += vr[i] * b_v[i];
    const float* hr = g_h + (size_t)b * RBM_H;            // g_h holds h2 here
    for (int i = tid; i < RBM_H; i += 256) acc -= hr[i] * b_h[i];
    if (tid < 8)  acc += g_pos[b * 8 + tid];              // 8 n-tiles (BN=128, N=1024)
    if (tid < 32) acc -= g_neg[b * 32 + tid];             // 32 n-tiles (BN=128, N=4096)
    __shared__ float red[256];
    red[tid] = acc;
    __syncthreads();
    for (int o = 128; o; o >>= 1) { if (tid < o) red[tid] += red[tid + o]; __syncthreads(); }
    if (tid == 0) out[b] = red[0];
}

// ---------------- launch ----------------
extern "C" void kernel_launch(void* const* d_in, const int* in_sizes, int n_in,
                              void* d_out, int out_size)
{
    const float* visible = (const float*)d_in[0];
    const float* b_v     = (const float*)d_in[1];
    const float* b_h     = (const float*)d_in[2];
    const float* W       = (const float*)d_in[3];
    const float* u_h0    = (const float*)d_in[4];
    const float* u_v     = (const float*)d_in[5];
    const float* u_h     = (const float*)d_in[6];
    float* out = (float*)d_out;

    float *WT, *hb, *vb, *pos, *neg;
    cudaGetSymbolAddress((void**)&WT,  g_WT);
    cudaGetSymbolAddress((void**)&hb,  g_h);
    cudaGetSymbolAddress((void**)&vb,  g_v);
    cudaGetSymbolAddress((void**)&pos, g_pos);
    cudaGetSymbolAddress((void**)&neg, g_neg);

    k_transpose<<<dim3(RBM_H / 32, RBM_V / 32), dim3(32, 8)>>>(W, WT);

    dim3 blk(128);
    dim3 gH(RBM_H / 128, RBM_B / 128);   // (8, 16)  = 128 CTAs
    dim3 gV(RBM_V / 128, RBM_B / 128);   // (32, 16) = 512 CTAs

    const size_t BV = (size_t)RBM_B * RBM_V;
    const size_t BH = (size_t)RBM_B * RBM_H;

    // positive phase: h0 | data, fused pos-score
    k_gemm_sample<1><<<gH, blk>>>(visible, W,  b_h, u_h0,        hb, pos,    RBM_V, RBM_H);
    // Gibbs chain: v,h,v,h,v
    k_gemm_sample<0><<<gV, blk>>>(hb,      WT, b_v, u_v + 0*BV,  vb, nullptr, RBM_H, RBM_V);
    k_gemm_sample<0><<<gH, blk>>>(vb,      W,  b_h, u_h + 0*BH,  hb, nullptr, RBM_V, RBM_H);
    k_gemm_sample<0><<<gV, blk>>>(hb,      WT, b_v, u_v + 1*BV,  vb, nullptr, RBM_H, RBM_V);
    k_gemm_sample<0><<<gH, blk>>>(vb,      W,  b_h, u_h + 1*BH,  hb, nullptr, RBM_V, RBM_H);
    // last v-step: fused neg-score
    k_gemm_sample<2><<<gV, blk>>>(hb,      WT, b_v, u_v + 2*BV,  vb, neg,     RBM_H, RBM_V);

    k_finalize<<<RBM_B, 256>>>(visible, b_v, b_h, out);
}

// round 8
// speedup vs baseline: 1.4575x; 1.0053x over previous
#include <cuda_runtime.h>
#include <math.h>

#define RBM_B 2048
#define RBM_V 4096
#define RBM_H 1024

// Scratch (device globals: allocation-free rule)
static __device__ float g_WT[(size_t)RBM_H * RBM_V];   // 16 MB  W transposed [H,V]
static __device__ float g_h [(size_t)RBM_B * RBM_H];   //  8 MB  current h
static __device__ float g_v [(size_t)RBM_B * RBM_V];   // 32 MB  current v
static __device__ float g_pos[RBM_B * 16];             // pos partials (16 n-tiles, BN=64)
static __device__ float g_neg[RBM_B * 64];             // neg partials (64 n-tiles, BN=64)

typedef unsigned long long u64;

// packed f32x2 FMA (full-rate fp32 on sm_103a; per-lane rounding == scalar FFMA)
__device__ __forceinline__ void ffma2(u64& d, u64 a, u64 b) {
    asm("fma.rn.f32x2 %0, %1, %2, %0;" : "+l"(d) : "l"(a), "l"(b));
}
__device__ __forceinline__ u64 dup32(float v) {
    unsigned u = __float_as_uint(v);
    return (u64)u | ((u64)u << 32);
}

// ---------------- transpose W[V,H] -> WT[H,V] ----------------
__global__ void k_transpose(const float* __restrict__ W, float* __restrict__ WT) {
    __shared__ float t[32][33];
    int h0 = blockIdx.x * 32, v0 = blockIdx.y * 32;
#pragma unroll
    for (int i = 0; i < 4; ++i)
        t[threadIdx.y + 8*i][threadIdx.x] =
            W[(size_t)(v0 + threadIdx.y + 8*i) * RBM_H + h0 + threadIdx.x];
    __syncthreads();
#pragma unroll
    for (int i = 0; i < 4; ++i)
        WT[(size_t)(h0 + threadIdx.y + 8*i) * RBM_V + v0 + threadIdx.x] =
            t[threadIdx.x][threadIdx.y + 8*i];
}

// ---------------- fused GEMM + bias + sigmoid-Bernoulli sample (+score) ----------------
// C[M,N] = A[M,K] * Bm[K,N]; A binary {0,1}.
// CRITICAL: one accumulator per output element, strict ascending-k fma.rn chain
// (bit-identical logits to all passing rounds). SIMD pairs along n.
// BM=128, BN=64, BK=16, 128 threads; thread tile 8m x 8n (32 FFMA2 / 6 LDS per kk).
// 3 CTAs/SM resident (12 warps) to hide barriers + prefetch latency; grids 256/1024.
// tx = tid&7 (n octet), ty = tid>>3 (m group). Thread n-cols: q*32 + tx*4, q = 0..1.
template<int SCORE>
__global__ __launch_bounds__(128, 3)
void k_gemm_sample(const float* __restrict__ A, const float* __restrict__ Bm,
                   const float* __restrict__ bias, const float* __restrict__ U,
                   float* __restrict__ Out, float* __restrict__ Score,
                   int K, int N)
{
    constexpr int BM = 128, BN = 64, BK = 16;
    __shared__ __align__(16) u64   As[2][BK][BM];      // dup-A: 32 KB
    __shared__ __align__(16) float Bs[2][BK][BN];      // plain B: 8 KB

    const int tid = threadIdx.x;
    const int tx = tid & 7, ty = tid >> 3;
    const int m0 = blockIdx.y * BM, n0 = blockIdx.x * BN;

    // A: one row per thread, 16 consecutive k. B: 16 rows, 8 floats per thread.
    const int brow = tid >> 3, bcol = (tid & 7) * 8;
    const float* Aload = A + (size_t)(m0 + tid) * K;
    const float* Bload = Bm + (size_t)brow * N + n0 + bcol;

    // acc[m 0..7][j 0..3]: u64 = fp32 pair, columns ((j>>1)*32 + tx*4 + 2*(j&1), +1)
    u64 acc[8][4];
#pragma unroll
    for (int m = 0; m < 8; ++m)
#pragma unroll
        for (int j = 0; j < 4; ++j) acc[m][j] = 0ull;

    float4 pa[4], pb[2];

    // ---- prologue: tile 0 ----
#pragma unroll
    for (int q = 0; q < 4; ++q) pa[q] = *(const float4*)(Aload + q * 4);
#pragma unroll
    for (int q = 0; q < 2; ++q) pb[q] = *(const float4*)(Bload + q * 4);
    {
#pragma unroll
        for (int c = 0; c < 16; ++c)
            As[0][c][tid] = dup32(((const float*)&pa[0])[c]);
#pragma unroll
        for (int q = 0; q < 2; ++q)
            *(float4*)&Bs[0][brow][bcol + q * 4] = pb[q];
    }
    __syncthreads();

    const int nk = K / BK;
    int buf = 0;
    for (int t = 0; t < nk; ++t) {
        if (t + 1 < nk) {
            const float* Ap = Aload + (t + 1) * BK;
            const float* Bp = Bload + (size_t)(t + 1) * BK * N;
#pragma unroll
            for (int q = 0; q < 4; ++q) pa[q] = *(const float4*)(Ap + q * 4);
#pragma unroll
            for (int q = 0; q < 2; ++q) pb[q] = *(const float4*)(Bp + q * 4);
        }
        // strict ascending-k serial accumulation (32 independent FFMA2 chains)
#pragma unroll
        for (int kk = 0; kk < BK; ++kk) {
            const ulonglong2* Au = (const ulonglong2*)&As[buf][kk][ty * 8];
            ulonglong2 a01 = Au[0], a23 = Au[1], a45 = Au[2], a67 = Au[3];
            u64 ap[8] = {a01.x, a01.y, a23.x, a23.y, a45.x, a45.y, a67.x, a67.y};
            u64 bp[4];
#pragma unroll
            for (int q = 0; q < 2; ++q) {
                ulonglong2 b2 = *(const ulonglong2*)&Bs[buf][kk][q * 32 + tx * 4];
                bp[q * 2] = b2.x; bp[q * 2 + 1] = b2.y;
            }
#pragma unroll
            for (int m = 0; m < 8; ++m)
#pragma unroll
                for (int j = 0; j < 4; ++j)
                    ffma2(acc[m][j], ap[m], bp[j]);
        }
        if (t + 1 < nk) {
            int nb = buf ^ 1;
#pragma unroll
            for (int c = 0; c < 16; ++c)
                As[nb][c][tid] = dup32(((const float*)&pa[0])[c]);
#pragma unroll
            for (int q = 0; q < 2; ++q)
                *(float4*)&Bs[nb][brow][bcol + q * 4] = pb[q];
        }
        __syncthreads();
        buf ^= 1;
    }

    // ---- epilogue: bias + sigmoid + Bernoulli + optional per-row score partial ----
    float biasv[8];
#pragma unroll
    for (int q = 0; q < 2; ++q)
        *(float4*)&biasv[q * 4] = *(const float4*)(bias + n0 + q * 32 + tx * 4);
#pragma unroll
    for (int m = 0; m < 8; ++m) {
        int gm = m0 + ty * 8 + m;
        float sp = 0.f;
#pragma unroll
        for (int q = 0; q < 2; ++q) {
            int gn = n0 + q * 32 + tx * 4;
            float4 u4 = *(const float4*)(U + (size_t)gm * N + gn);
            float2 e0 = *(float2*)&acc[m][q * 2];
            float2 e1 = *(float2*)&acc[m][q * 2 + 1];
            float l[4] = { e0.x + biasv[q*4],   e0.y + biasv[q*4+1],
                           e1.x + biasv[q*4+2], e1.y + biasv[q*4+3] };
            float s[4];
#pragma unroll
            for (int j = 0; j < 4; ++j) {
                float pr = 1.0f / (1.0f + expf(-l[j]));   // libdevice expf + IEEE div
                s[j] = (pr > ((const float*)&u4)[j]) ? 1.0f : 0.0f;
            }
            *(float4*)(Out + (size_t)gm * N + gn) = make_float4(s[0], s[1], s[2], s[3]);
            if (SCORE) sp += s[0]*l[0] + s[1]*l[1] + s[2]*l[2] + s[3]*l[3];
        }
        if (SCORE) {
            sp += __shfl_xor_sync(0xffffffffu, sp, 1);
            sp += __shfl_xor_sync(0xffffffffu, sp, 2);
            sp += __shfl_xor_sync(0xffffffffu, sp, 4);
            if (tx == 0) Score[(size_t)gm * gridDim.x + blockIdx.x] = sp;
        }
    }
}

// ---------------- finalize: out[b] = (v.b_v + pos) - (neg + h2.b_h) ----------------
__global__ void k_finalize(const float* __restrict__ visible, const float* __restrict__ b_v,
                           const float* __restrict__ b_h, float* __restrict__ out)
{
    int b = blockIdx.x, tid = threadIdx.x;
    float acc = 0.f;
    const float* vr = visible + (size_t)b * RBM_V;
    for (int i = tid; i < RBM_V; i += 256) acc += vr[i] * b_v[i];
    const float* hr = g_h + (size_t)b * RBM_H;            // g_h holds h2 here
    for (int i = tid; i < RBM_H; i += 256) acc -= hr[i] * b_h[i];
    if (tid < 16) acc += g_pos[b * 16 + tid];             // 16 n-tiles (BN=64, N=1024)
    if (tid < 64) acc -= g_neg[b * 64 + tid];             // 64 n-tiles (BN=64, N=4096)
    __shared__ float red[256];
    red[tid] = acc;
    __syncthreads();
    for (int o = 128; o; o >>= 1) { if (tid < o) red[tid] += red[tid + o]; __syncthreads(); }
    if (tid == 0) out[b] = red[0];
}

// ---------------- launch ----------------
extern "C" void kernel_launch(void* const* d_in, const int* in_sizes, int n_in,
                              void* d_out, int out_size)
{
    const float* visible = (const float*)d_in[0];
    const float* b_v     = (const float*)d_in[1];
    const float* b_h     = (const float*)d_in[2];
    const float* W       = (const float*)d_in[3];
    const float* u_h0    = (const float*)d_in[4];
    const float* u_v     = (const float*)d_in[5];
    const float* u_h     = (const float*)d_in[6];
    float* out = (float*)d_out;

    float *WT, *hb, *vb, *pos, *neg;
    cudaGetSymbolAddress((void**)&WT,  g_WT);
    cudaGetSymbolAddress((void**)&hb,  g_h);
    cudaGetSymbolAddress((void**)&vb,  g_v);
    cudaGetSymbolAddress((void**)&pos, g_pos);
    cudaGetSymbolAddress((void**)&neg, g_neg);

    k_transpose<<<dim3(RBM_H / 32, RBM_V / 32), dim3(32, 8)>>>(W, WT);

    dim3 blk(128);
    dim3 gH(RBM_H / 64, RBM_B / 128);   // (16, 16) = 256 CTAs
    dim3 gV(RBM_V / 64, RBM_B / 128);   // (64, 16) = 1024 CTAs

    const size_t BV = (size_t)RBM_B * RBM_V;
    const size_t BH = (size_t)RBM_B * RBM_H;

    // positive phase: h0 | data, fused pos-score
    k_gemm_sample<1><<<gH, blk>>>(visible, W,  b_h, u_h0,        hb, pos,    RBM_V, RBM_H);
    // Gibbs chain: v,h,v,h,v
    k_gemm_sample<0><<<gV, blk>>>(hb,      WT, b_v, u_v + 0*BV,  vb, nullptr, RBM_H, RBM_V);
    k_gemm_sample<0><<<gH, blk>>>(vb,      W,  b_h, u_h + 0*BH,  hb, nullptr, RBM_V, RBM_H);
    k_gemm_sample<0><<<gV, blk>>>(hb,      WT, b_v, u_v + 1*BV,  vb, nullptr, RBM_H, RBM_V);
    k_gemm_sample<0><<<gH, blk>>>(vb,      W,  b_h, u_h + 1*BH,  hb, nullptr, RBM_V, RBM_H);
    // last v-step: fused neg-score
    k_gemm_sample<2><<<gV, blk>>>(hb,      WT, b_v, u_v + 2*BV,  vb, neg,     RBM_H, RBM_V);

    k_finalize<<<RBM_B, 256>>>(visible, b_v, b_h, out);
}